// round 14
// baseline (speedup 1.0000x reference)
#include <cuda_runtime.h>
#include <math.h>

// ---------------------------------------------------------------------------
// simpleGNN: 2x GraphConv(128->128) + ReLU, segment_max pool, Linear(128->1),
// sigmoid.
// GEMM-first reordering; CSR gather (no float atomics); parallel CSR build.
// R14 == R13 (infra failure last round, re-bench):
//   break the accumulator RAW chain in the GEMM -- the 3 split-TF32 mma
//   terms per accumulator were issued back-to-back (serialized on c).
//   Now batched: all hh, then all hl, then all lh (dep distance 16).
//   mma asm no longer volatile (register-only effects).
// ---------------------------------------------------------------------------

#define MAX_NODES 50000
#define MAX_EDGES 640000
#define FDIM      128
#define SCAN_CHUNK 1024
#define MAX_PARTS  64

#define ASTR 20
#define BSTR 133
#define A_TILE (128 * ASTR)                  // floats per A buffer
#define GEMM_SMEM_FLOATS (128 * BSTR + 2 * A_TILE)
#define GEMM_SMEM_BYTES  (GEMM_SMEM_FLOATS * 4)

typedef unsigned int u32;

__device__ float g_Z    [MAX_NODES * FDIM];
__device__ float g_H1   [MAX_NODES * FDIM];
__device__ float g_H2   [MAX_NODES * FDIM];
__device__ int   g_ei   [2 * MAX_EDGES];
__device__ int   g_batch[MAX_NODES];
__device__ int   g_deg  [MAX_NODES];
__device__ int   g_off  [MAX_NODES + 1];
__device__ int   g_part [MAX_PARTS];
__device__ int   g_src  [MAX_EDGES];
__device__ float g_wp   [MAX_EDGES];

// ---------------- tf32 helpers ---------------------------------------------
__device__ __forceinline__ u32 f2tf32(float f) {
    u32 u;
    asm("cvt.rna.tf32.f32 %0, %1;" : "=r"(u) : "f"(f));
    return u;
}
__device__ __forceinline__ void split_tf32(float f, u32& hi, u32& lo) {
    hi = f2tf32(f);
    lo = f2tf32(f - __uint_as_float(hi));
}
// Register-only effects: NOT volatile, so ptxas may interleave with cvt work.
__device__ __forceinline__ void mma_tf32(float c[4], const u32 a[4], const u32 b[2]) {
    asm("mma.sync.aligned.m16n8k8.row.col.f32.tf32.tf32.f32 "
        "{%0,%1,%2,%3}, {%4,%5,%6,%7}, {%8,%9}, {%0,%1,%2,%3};"
        : "+f"(c[0]), "+f"(c[1]), "+f"(c[2]), "+f"(c[3])
        : "r"(a[0]), "r"(a[1]), "r"(a[2]), "r"(a[3]), "r"(b[0]), "r"(b[1]));
}
__device__ __forceinline__ void cp_async16(u32 smem_dst, const void* gsrc, int src_bytes) {
    asm volatile("cp.async.ca.shared.global [%0], [%1], 16, %2;"
                 :: "r"(smem_dst), "l"(gsrc), "r"(src_bytes));
}
__device__ __forceinline__ void cp_async_commit() {
    asm volatile("cp.async.commit_group;");
}
__device__ __forceinline__ void cp_async_wait0() {
    asm volatile("cp.async.wait_group 0;");
}

// ---------------------------------------------------------------------------
// convert + histogram + dtype detect (fused).
// ---------------------------------------------------------------------------
__global__ void __launch_bounds__(256)
convert_hist(const int* __restrict__ ei,
             const int* __restrict__ batch,
             int E, int Nn)
{
    __shared__ int s_is64;
    if (threadIdx.x == 0) {
        int any = 0;
        #pragma unroll
        for (int k = 1; k < 128; k += 2) any |= ei[k];
        s_is64 = (any == 0);
    }
    __syncthreads();
    int f = s_is64;

    int i = blockIdx.x * blockDim.x + threadIdx.x;
    int twoE = 2 * E;
    if (i < twoE) {
        int v = f ? ei[2 * i] : ei[i];
        g_ei[i] = v;
        if (i >= E && (unsigned)v < (unsigned)Nn)
            atomicAdd(&g_deg[v], 1);
    }
    if (i < Nn)
        g_batch[i] = f ? batch[2 * i] : batch[i];
}

// ---------------------------------------------------------------------------
// Blocked exclusive scan of g_deg -> g_off.
// ---------------------------------------------------------------------------
__global__ void __launch_bounds__(256)
partial_kernel(int Nn)
{
    __shared__ int red[256];
    int t = threadIdx.x;
    int base = blockIdx.x * SCAN_CHUNK + t * 4;
    int s = 0;
    #pragma unroll
    for (int j = 0; j < 4; j++) {
        int idx = base + j;
        s += (idx < Nn) ? g_deg[idx] : 0;
    }
    red[t] = s;
    __syncthreads();
    #pragma unroll
    for (int d = 128; d > 0; d >>= 1) {
        if (t < d) red[t] += red[t + d];
        __syncthreads();
    }
    if (t == 0) g_part[blockIdx.x] = red[0];
}

__global__ void __launch_bounds__(64)
scan_part_kernel(int NB, int Nn)
{
    __shared__ int s[MAX_PARTS];
    int t = threadIdx.x;
    s[t] = (t < NB) ? g_part[t] : 0;
    __syncthreads();
    #pragma unroll
    for (int d = 1; d < MAX_PARTS; d <<= 1) {
        int v = (t >= d) ? s[t - d] : 0;
        __syncthreads();
        s[t] += v;
        __syncthreads();
    }
    if (t < NB) g_part[t] = (t == 0) ? 0 : s[t - 1];
    if (t == MAX_PARTS - 1) g_off[Nn] = s[MAX_PARTS - 1];
}

__global__ void __launch_bounds__(256)
writeoff_kernel(int Nn)
{
    __shared__ int sums[256];
    int t = threadIdx.x;
    int base = blockIdx.x * SCAN_CHUNK + t * 4;

    int local[4];
    int s = 0;
    #pragma unroll
    for (int j = 0; j < 4; j++) {
        int idx = base + j;
        local[j] = (idx < Nn) ? g_deg[idx] : 0;
        s += local[j];
    }
    sums[t] = s;
    __syncthreads();
    #pragma unroll
    for (int d = 1; d < 256; d <<= 1) {
        int v = (t >= d) ? sums[t - d] : 0;
        __syncthreads();
        sums[t] += v;
        __syncthreads();
    }
    int run = g_part[blockIdx.x] + ((t == 0) ? 0 : sums[t - 1]);
    #pragma unroll
    for (int j = 0; j < 4; j++) {
        int idx = base + j;
        if (idx < Nn) {
            g_off[idx] = run;
            g_deg[idx] = run;
            run += local[j];
        }
    }
}

__global__ void __launch_bounds__(256)
fill_kernel(const float* __restrict__ ew, int E, int Nn)
{
    int i = blockIdx.x * blockDim.x + threadIdx.x;
    if (i >= E) return;
    int s = g_ei[i];
    int d = g_ei[E + i];
    if ((unsigned)s >= (unsigned)Nn || (unsigned)d >= (unsigned)Nn) return;
    int p = atomicAdd(&g_deg[d], 1);
    g_src[p] = s;
    g_wp[p]  = ew[i];
}

// ---------------------------------------------------------------------------
// Dual-output GEMM on tensor cores (split-TF32 in registers, 3 mma terms,
// batched hh/hl/lh issue order -> accumulator dep distance 16).
//   y==0: Z[m,:] = act(A[m,:]) @ Wrel       (cols 0..127)
//   y==1: H[m,:] = act(A[m,:]) @ Wroot + b  (cols 128..255)
// Block tile 128x128, BK=16, 256 threads (8 warps: 4m x 2n, warp tile 32x64).
// Dynamic smem: B resident for whole block (stride 133, conflict-free),
// A double-buffered via cp.async (stride 20).
// ---------------------------------------------------------------------------
template<bool RELU>
__global__ void __launch_bounds__(256)
gemm_dual(const float* __restrict__ A,
          const float* __restrict__ Wrel,
          const float* __restrict__ Wroot,
          const float* __restrict__ bias,
          float* __restrict__ Z,
          float* __restrict__ H,
          int M)
{
    extern __shared__ __align__(16) float smem[];
    float* Bs = smem;                      // 128 * BSTR
    float* As = smem + 128 * BSTR;         // 2 * A_TILE

    const int tid   = threadIdx.x;
    const int wid   = tid >> 5;
    const int lane  = tid & 31;
    const int grp   = lane >> 2;      // 0..7
    const int tig   = lane & 3;       // 0..3
    const int warpM = wid >> 1;       // 0..3  (32-row strip)
    const int warpN = wid & 1;        // 0..1  (64-col strip)
    const int row0  = blockIdx.x * 128;
    const bool relHalf = (blockIdx.y == 0);
    const float* __restrict__ W = relHalf ? Wrel : Wroot;

    const u32 As_u32 = (u32)__cvta_generic_to_shared(As);

    // ---- one-time: load FULL B (128x128) into resident smem ----
    #pragma unroll
    for (int it = 0; it < 16; it++) {
        int idx = tid + it * 256;          // 0..4095 float4s
        int kr  = idx >> 5;                // 0..127
        int nq  = idx & 31;                // float4 col
        float4 b = *(const float4*)(W + (size_t)kr * 128 + nq * 4);
        int base = kr * BSTR + nq * 4;     // odd stride -> scalar stores
        Bs[base + 0] = b.x;
        Bs[base + 1] = b.y;
        Bs[base + 2] = b.z;
        Bs[base + 3] = b.w;
    }

    // ---- prefetch A tile 0 ----
    {
        #pragma unroll
        for (int j = 0; j < 2; j++) {
            int idx = tid + j * 256;
            int r   = idx >> 2;
            int kq  = idx & 3;
            int gr  = row0 + r;
            int ok  = (gr < M);
            const float* src = A + (size_t)(ok ? gr : 0) * 128 + kq * 4;
            u32 dst = As_u32 + (u32)(r * ASTR + kq * 4) * 4u;
            cp_async16(dst, src, ok ? 16 : 0);
        }
        cp_async_commit();
    }

    float acc[2][8][4];
    #pragma unroll
    for (int mt = 0; mt < 2; mt++)
        #pragma unroll
        for (int nt = 0; nt < 8; nt++)
            #pragma unroll
            for (int c = 0; c < 4; c++) acc[mt][nt][c] = 0.f;

    for (int kt = 0; kt < 8; kt++) {
        const int k0  = kt * 16;
        const int buf = kt & 1;

        cp_async_wait0();
        __syncthreads();   // A tile ready; orders B STS (iter 0) and buffer reuse

        // prefetch next A tile into the other buffer
        if (kt < 7) {
            int nk0 = k0 + 16;
            #pragma unroll
            for (int j = 0; j < 2; j++) {
                int idx = tid + j * 256;
                int r   = idx >> 2;
                int kq  = idx & 3;
                int gr  = row0 + r;
                int ok  = (gr < M);
                const float* src = A + (size_t)(ok ? gr : 0) * 128 + nk0 + kq * 4;
                u32 dst = As_u32 + (u32)(((buf ^ 1) * A_TILE) + r * ASTR + kq * 4) * 4u;
                cp_async16(dst, src, ok ? 16 : 0);
            }
            cp_async_commit();
        }

        const float* Ab = As + buf * A_TILE;

        #pragma unroll
        for (int ks = 0; ks < 2; ks++) {
            const int k = ks * 8;
            u32 ah[2][4], al[2][4], bh[8][2], bl[8][2];
            #pragma unroll
            for (int mt = 0; mt < 2; mt++) {
                int m  = warpM * 32 + mt * 16 + grp;
                int b0 = m * ASTR + k + tig;
                float f0 = Ab[b0];
                float f1 = Ab[b0 + 8 * ASTR];
                float f2 = Ab[b0 + 4];
                float f3 = Ab[b0 + 8 * ASTR + 4];
                if (RELU) {
                    f0 = fmaxf(f0, 0.f); f1 = fmaxf(f1, 0.f);
                    f2 = fmaxf(f2, 0.f); f3 = fmaxf(f3, 0.f);
                }
                split_tf32(f0, ah[mt][0], al[mt][0]);
                split_tf32(f1, ah[mt][1], al[mt][1]);
                split_tf32(f2, ah[mt][2], al[mt][2]);
                split_tf32(f3, ah[mt][3], al[mt][3]);
            }
            #pragma unroll
            for (int nt = 0; nt < 8; nt++) {
                int n  = warpN * 64 + nt * 8 + grp;
                int b0 = (k0 + k + tig) * BSTR + n;
                float f0 = Bs[b0];
                float f1 = Bs[b0 + 4 * BSTR];
                split_tf32(f0, bh[nt][0], bl[nt][0]);
                split_tf32(f1, bh[nt][1], bl[nt][1]);
            }
            // Batched issue: 16 independent mmas between dependent writes to
            // the same accumulator (was 3 back-to-back RAW-serialized mmas).
            #pragma unroll
            for (int mt = 0; mt < 2; mt++)
                #pragma unroll
                for (int nt = 0; nt < 8; nt++)
                    mma_tf32(acc[mt][nt], ah[mt], bh[nt]);   // hi*hi
            #pragma unroll
            for (int mt = 0; mt < 2; mt++)
                #pragma unroll
                for (int nt = 0; nt < 8; nt++)
                    mma_tf32(acc[mt][nt], ah[mt], bl[nt]);   // hi*lo
            #pragma unroll
            for (int mt = 0; mt < 2; mt++)
                #pragma unroll
                for (int nt = 0; nt < 8; nt++)
                    mma_tf32(acc[mt][nt], al[mt], bh[nt]);   // lo*hi
        }
        __syncthreads();   // all reads of buf done before next prefetch overwrites
    }

    // ---- epilogue ----
    #pragma unroll
    for (int mt = 0; mt < 2; mt++) {
        int r0 = row0 + warpM * 32 + mt * 16 + grp;
        int r1 = r0 + 8;
        #pragma unroll
        for (int nt = 0; nt < 8; nt++) {
            int c = warpN * 64 + nt * 8 + 2 * tig;   // 0..126
            if (relHalf) {
                if (r0 < M) *(float2*)(Z + (size_t)r0 * 128 + c) =
                    make_float2(acc[mt][nt][0], acc[mt][nt][1]);
                if (r1 < M) *(float2*)(Z + (size_t)r1 * 128 + c) =
                    make_float2(acc[mt][nt][2], acc[mt][nt][3]);
            } else {
                float bx = bias[c], by = bias[c + 1];
                if (r0 < M) *(float2*)(H + (size_t)r0 * 128 + c) =
                    make_float2(acc[mt][nt][0] + bx, acc[mt][nt][1] + by);
                if (r1 < M) *(float2*)(H + (size_t)r1 * 128 + c) =
                    make_float2(acc[mt][nt][2] + bx, acc[mt][nt][3] + by);
            }
        }
    }
}

// ---------------------------------------------------------------------------
// CSR gather: one warp per dst node, 8-way unrolled, no atomics.
// ---------------------------------------------------------------------------
__global__ void __launch_bounds__(256)
gather_kernel(const float* __restrict__ Z,
              float* __restrict__ H,
              int Nn)
{
    int warp = (int)((blockIdx.x * (unsigned)blockDim.x + threadIdx.x) >> 5);
    int lane = threadIdx.x & 31;
    if (warp >= Nn) return;

    int lo = g_off[warp];
    int hi = g_off[warp + 1];
    if (lo == hi) return;

    float4 acc = make_float4(0.f, 0.f, 0.f, 0.f);
    int e = lo;
    for (; e + 7 < hi; e += 8) {
        int   s[8]; float w[8]; float4 v[8];
        #pragma unroll
        for (int j = 0; j < 8; j++) { s[j] = g_src[e + j]; w[j] = g_wp[e + j]; }
        #pragma unroll
        for (int j = 0; j < 8; j++)
            v[j] = ((const float4*)(Z + (size_t)s[j] * 128))[lane];
        #pragma unroll
        for (int j = 0; j < 8; j++) {
            acc.x = fmaf(w[j], v[j].x, acc.x);
            acc.y = fmaf(w[j], v[j].y, acc.y);
            acc.z = fmaf(w[j], v[j].z, acc.z);
            acc.w = fmaf(w[j], v[j].w, acc.w);
        }
    }
    for (; e < hi; e++) {
        int   s0 = g_src[e];
        float w0 = g_wp[e];
        float4 v0 = ((const float4*)(Z + (size_t)s0 * 128))[lane];
        acc.x = fmaf(w0, v0.x, acc.x); acc.y = fmaf(w0, v0.y, acc.y);
        acc.z = fmaf(w0, v0.z, acc.z); acc.w = fmaf(w0, v0.w, acc.w);
    }

    float4* hp = ((float4*)(H + (size_t)warp * 128)) + lane;
    float4 h = *hp;
    h.x += acc.x; h.y += acc.y; h.z += acc.z; h.w += acc.w;
    *hp = h;
}

// ---------------------------------------------------------------------------
// Pool + linear + sigmoid; re-zeroes g_deg for the next call.
// ---------------------------------------------------------------------------
__global__ void __launch_bounds__(128)
pool_kernel(const float* __restrict__ H2,
            const float* __restrict__ Wlin,
            const float* __restrict__ blin,
            float* __restrict__ out,
            int Nn)
{
    int g = blockIdx.x;
    int t = threadIdx.x;

    for (int i = g * 128 + t; i < Nn; i += gridDim.x * 128)
        g_deg[i] = 0;

    __shared__ int s_range[2];
    if (t < 2) {
        int target = g + t;
        int lo = 0, hi = Nn;
        while (lo < hi) {
            int mid = (lo + hi) >> 1;
            if (g_batch[mid] < target) lo = mid + 1; else hi = mid;
        }
        s_range[t] = lo;
    }
    __syncthreads();
    int lo = s_range[0], hi = s_range[1];

    float m = -INFINITY;
    for (int n = lo; n < hi; n++)
        m = fmaxf(m, H2[(size_t)n * 128 + t]);
    if (hi > lo) m = fmaxf(m, 0.0f);

    float v = m * Wlin[t];

    __shared__ float red[128];
    red[t] = v;
    __syncthreads();
    #pragma unroll
    for (int s = 64; s > 0; s >>= 1) {
        if (t < s) red[t] += red[t + s];
        __syncthreads();
    }
    if (t == 0) {
        float logit = red[0] + blin[0];
        out[g] = 1.0f / (1.0f + expf(-logit));
    }
}

// ---------------------------------------------------------------------------
extern "C" void kernel_launch(void* const* d_in, const int* in_sizes, int n_in,
                              void* d_out, int out_size)
{
    const float* x      = (const float*) d_in[0];
    const int*   ei     = (const int*)   d_in[1];
    const int*   batch  = (const int*)   d_in[2];
    const float* ew     = (const float*) d_in[3];
    const float* W1rel  = (const float*) d_in[4];
    const float* b1     = (const float*) d_in[5];
    const float* W1root = (const float*) d_in[6];
    const float* W2rel  = (const float*) d_in[7];
    const float* b2     = (const float*) d_in[8];
    const float* W2root = (const float*) d_in[9];
    const float* Wlin   = (const float*) d_in[10];
    const float* blin   = (const float*) d_in[11];
    float* out = (float*)d_out;

    int M = in_sizes[0] / 128;
    int E = in_sizes[1] / 2;
    int G = out_size;
    if (M > MAX_NODES) M = MAX_NODES;
    if (E > MAX_EDGES) E = MAX_EDGES;

    float *Z, *H1, *H2;
    cudaGetSymbolAddress((void**)&Z,  g_Z);
    cudaGetSymbolAddress((void**)&H1, g_H1);
    cudaGetSymbolAddress((void**)&H2, g_H2);

    // Allow >48KB dynamic smem for the GEMM.  Idempotent host-side attribute
    // registration (not a stream op; safe under graph capture).
    cudaFuncSetAttribute(gemm_dual<false>,
        cudaFuncAttributeMaxDynamicSharedMemorySize, GEMM_SMEM_BYTES);
    cudaFuncSetAttribute(gemm_dual<true>,
        cudaFuncAttributeMaxDynamicSharedMemorySize, GEMM_SMEM_BYTES);

    int NB = (M + SCAN_CHUNK - 1) / SCAN_CHUNK;
    dim3 ggrid((M + 127) / 128, 2);
    int gatherBlocks = (M * 32 + 255) / 256;

    // 1: convert + detect + histogram
    {
        int work = 2 * E;
        if (M > work) work = M;
        convert_hist<<<(work + 255) / 256, 256>>>(ei, batch, E, M);
    }
    // 2-3: scan front half
    partial_kernel  <<<NB, 256>>>(M);
    scan_part_kernel<<<1, 64>>>(NB, M);
    // 4: Layer-1 GEMM (no CSR dependence) -- profiled launch
    gemm_dual<false><<<ggrid, 256, GEMM_SMEM_BYTES>>>(x, W1rel, W1root, b1, Z, H1, M);
    // 5-6: finish CSR build
    writeoff_kernel <<<NB, 256>>>(M);
    fill_kernel<<<(E + 255) / 256, 256>>>(ew, E, M);
    // 7: Layer-1 gather
    gather_kernel<<<gatherBlocks, 256>>>(Z, H1, M);
    // 8-9: Layer 2
    gemm_dual<true><<<ggrid, 256, GEMM_SMEM_BYTES>>>(H1, W2rel, W2root, b2, Z, H2, M);
    gather_kernel<<<gatherBlocks, 256>>>(Z, H2, M);
    // 10: Pool + linear + sigmoid (+ deg re-zero)
    pool_kernel<<<G, 128>>>(H2, Wlin, blin, out, M);
}

// round 16
// speedup vs baseline: 1.2039x; 1.2039x over previous
#include <cuda_runtime.h>
#include <math.h>

// ---------------------------------------------------------------------------
// simpleGNN: 2x GraphConv(128->128) + ReLU, segment_max pool, Linear(128->1),
// sigmoid.
// GEMM-first reordering; CSR gather (no float atomics); parallel CSR build.
// R16 == R15 (infra failure last round, re-bench):
//   GEMM switched from mma.m16n8k8.tf32 (3-term split) to
//   mma.m16n8k16.bf16 (3-term truncation split: hh+hl+lh).  K per mma
//   doubles -> mma instruction count halves.  R12/R14 showed tensor
//   pinned at ~44% regardless of scheduling => per-instruction dispatch
//   ceiling; only fewer instructions can help.
//   Split: hi = truncate_bf16(f) (residual exact in fp32), lo = bf16_rn(r).
//   Missing lo*lo term ~2^-16 relative -> rel_err ~1e-5 (budget 1e-3).
// ---------------------------------------------------------------------------

#define MAX_NODES 50000
#define MAX_EDGES 640000
#define FDIM      128
#define SCAN_CHUNK 1024
#define MAX_PARTS  64

#define ASTR 20
#define BSTR 133
#define A_TILE (128 * ASTR)                  // floats per A buffer
#define GEMM_SMEM_FLOATS (128 * BSTR + 2 * A_TILE)
#define GEMM_SMEM_BYTES  (GEMM_SMEM_FLOATS * 4)

typedef unsigned int u32;

__device__ float g_Z    [MAX_NODES * FDIM];
__device__ float g_H1   [MAX_NODES * FDIM];
__device__ float g_H2   [MAX_NODES * FDIM];
__device__ int   g_ei   [2 * MAX_EDGES];
__device__ int   g_batch[MAX_NODES];
__device__ int   g_deg  [MAX_NODES];
__device__ int   g_off  [MAX_NODES + 1];
__device__ int   g_part [MAX_PARTS];
__device__ int   g_src  [MAX_EDGES];
__device__ float g_wp   [MAX_EDGES];

// ---------------- bf16 split helpers ----------------------------------------
// hi = bf16 truncation of f (top 16 bits of the fp32 pattern).  The residual
// r = f - hi is EXACT in fp32 (low mantissa bits).  lo = bf16_rn(r).
// pack_hi packs hi(f0) (low half) and hi(f1) (high half) with one PRMT.
__device__ __forceinline__ u32 pack_bf16_hi(float f0, float f1) {
    u32 d;
    asm("prmt.b32 %0, %1, %2, 0x7632;"
        : "=r"(d) : "r"(__float_as_uint(f0)), "r"(__float_as_uint(f1)));
    return d;
}
__device__ __forceinline__ u32 pack_bf16_lo(float f0, float f1) {
    float t0 = __uint_as_float(__float_as_uint(f0) & 0xFFFF0000u);
    float t1 = __uint_as_float(__float_as_uint(f1) & 0xFFFF0000u);
    float r0 = f0 - t0;
    float r1 = f1 - t1;
    u32 d;
    // d<15:0> = bf16(r0), d<31:16> = bf16(r1)
    asm("cvt.rn.bf16x2.f32 %0, %1, %2;" : "=r"(d) : "f"(r1), "f"(r0));
    return d;
}
// Register-only effects: NOT volatile, so ptxas may interleave freely.
__device__ __forceinline__ void mma_bf16(float c[4], const u32 a[4], const u32 b[2]) {
    asm("mma.sync.aligned.m16n8k16.row.col.f32.bf16.bf16.f32 "
        "{%0,%1,%2,%3}, {%4,%5,%6,%7}, {%8,%9}, {%0,%1,%2,%3};"
        : "+f"(c[0]), "+f"(c[1]), "+f"(c[2]), "+f"(c[3])
        : "r"(a[0]), "r"(a[1]), "r"(a[2]), "r"(a[3]), "r"(b[0]), "r"(b[1]));
}
__device__ __forceinline__ void cp_async16(u32 smem_dst, const void* gsrc, int src_bytes) {
    asm volatile("cp.async.ca.shared.global [%0], [%1], 16, %2;"
                 :: "r"(smem_dst), "l"(gsrc), "r"(src_bytes));
}
__device__ __forceinline__ void cp_async_commit() {
    asm volatile("cp.async.commit_group;");
}
__device__ __forceinline__ void cp_async_wait0() {
    asm volatile("cp.async.wait_group 0;");
}

// ---------------------------------------------------------------------------
// convert + histogram + dtype detect (fused).
// ---------------------------------------------------------------------------
__global__ void __launch_bounds__(256)
convert_hist(const int* __restrict__ ei,
             const int* __restrict__ batch,
             int E, int Nn)
{
    __shared__ int s_is64;
    if (threadIdx.x == 0) {
        int any = 0;
        #pragma unroll
        for (int k = 1; k < 128; k += 2) any |= ei[k];
        s_is64 = (any == 0);
    }
    __syncthreads();
    int f = s_is64;

    int i = blockIdx.x * blockDim.x + threadIdx.x;
    int twoE = 2 * E;
    if (i < twoE) {
        int v = f ? ei[2 * i] : ei[i];
        g_ei[i] = v;
        if (i >= E && (unsigned)v < (unsigned)Nn)
            atomicAdd(&g_deg[v], 1);
    }
    if (i < Nn)
        g_batch[i] = f ? batch[2 * i] : batch[i];
}

// ---------------------------------------------------------------------------
// Blocked exclusive scan of g_deg -> g_off.
// ---------------------------------------------------------------------------
__global__ void __launch_bounds__(256)
partial_kernel(int Nn)
{
    __shared__ int red[256];
    int t = threadIdx.x;
    int base = blockIdx.x * SCAN_CHUNK + t * 4;
    int s = 0;
    #pragma unroll
    for (int j = 0; j < 4; j++) {
        int idx = base + j;
        s += (idx < Nn) ? g_deg[idx] : 0;
    }
    red[t] = s;
    __syncthreads();
    #pragma unroll
    for (int d = 128; d > 0; d >>= 1) {
        if (t < d) red[t] += red[t + d];
        __syncthreads();
    }
    if (t == 0) g_part[blockIdx.x] = red[0];
}

__global__ void __launch_bounds__(64)
scan_part_kernel(int NB, int Nn)
{
    __shared__ int s[MAX_PARTS];
    int t = threadIdx.x;
    s[t] = (t < NB) ? g_part[t] : 0;
    __syncthreads();
    #pragma unroll
    for (int d = 1; d < MAX_PARTS; d <<= 1) {
        int v = (t >= d) ? s[t - d] : 0;
        __syncthreads();
        s[t] += v;
        __syncthreads();
    }
    if (t < NB) g_part[t] = (t == 0) ? 0 : s[t - 1];
    if (t == MAX_PARTS - 1) g_off[Nn] = s[MAX_PARTS - 1];
}

__global__ void __launch_bounds__(256)
writeoff_kernel(int Nn)
{
    __shared__ int sums[256];
    int t = threadIdx.x;
    int base = blockIdx.x * SCAN_CHUNK + t * 4;

    int local[4];
    int s = 0;
    #pragma unroll
    for (int j = 0; j < 4; j++) {
        int idx = base + j;
        local[j] = (idx < Nn) ? g_deg[idx] : 0;
        s += local[j];
    }
    sums[t] = s;
    __syncthreads();
    #pragma unroll
    for (int d = 1; d < 256; d <<= 1) {
        int v = (t >= d) ? sums[t - d] : 0;
        __syncthreads();
        sums[t] += v;
        __syncthreads();
    }
    int run = g_part[blockIdx.x] + ((t == 0) ? 0 : sums[t - 1]);
    #pragma unroll
    for (int j = 0; j < 4; j++) {
        int idx = base + j;
        if (idx < Nn) {
            g_off[idx] = run;
            g_deg[idx] = run;
            run += local[j];
        }
    }
}

__global__ void __launch_bounds__(256)
fill_kernel(const float* __restrict__ ew, int E, int Nn)
{
    int i = blockIdx.x * blockDim.x + threadIdx.x;
    if (i >= E) return;
    int s = g_ei[i];
    int d = g_ei[E + i];
    if ((unsigned)s >= (unsigned)Nn || (unsigned)d >= (unsigned)Nn) return;
    int p = atomicAdd(&g_deg[d], 1);
    g_src[p] = s;
    g_wp[p]  = ew[i];
}

// ---------------------------------------------------------------------------
// Dual-output GEMM on tensor cores (bf16 m16n8k16, 3-term truncation split,
// batched hh/hl/lh issue order).
//   y==0: Z[m,:] = act(A[m,:]) @ Wrel       (cols 0..127)
//   y==1: H[m,:] = act(A[m,:]) @ Wroot + b  (cols 128..255)
// Block tile 128x128, BK=16 (one k16 mma group per tile), 256 threads
// (8 warps: 4m x 2n, warp tile 32x64).
// Dynamic smem: B resident fp32 for whole block (stride 133), A fp32
// double-buffered via cp.async (stride 20).  bf16 hi/lo packing in registers
// at fragment-load time.
// ---------------------------------------------------------------------------
template<bool RELU>
__global__ void __launch_bounds__(256)
gemm_dual(const float* __restrict__ A,
          const float* __restrict__ Wrel,
          const float* __restrict__ Wroot,
          const float* __restrict__ bias,
          float* __restrict__ Z,
          float* __restrict__ H,
          int M)
{
    extern __shared__ __align__(16) float smem[];
    float* Bs = smem;                      // 128 * BSTR
    float* As = smem + 128 * BSTR;         // 2 * A_TILE

    const int tid   = threadIdx.x;
    const int wid   = tid >> 5;
    const int lane  = tid & 31;
    const int grp   = lane >> 2;      // 0..7
    const int tig   = lane & 3;       // 0..3
    const int warpM = wid >> 1;       // 0..3  (32-row strip)
    const int warpN = wid & 1;        // 0..1  (64-col strip)
    const int row0  = blockIdx.x * 128;
    const bool relHalf = (blockIdx.y == 0);
    const float* __restrict__ W = relHalf ? Wrel : Wroot;

    const u32 As_u32 = (u32)__cvta_generic_to_shared(As);

    // ---- one-time: load FULL B (128x128 fp32) into resident smem ----
    #pragma unroll
    for (int it = 0; it < 16; it++) {
        int idx = tid + it * 256;          // 0..4095 float4s
        int kr  = idx >> 5;                // 0..127
        int nq  = idx & 31;                // float4 col
        float4 b = *(const float4*)(W + (size_t)kr * 128 + nq * 4);
        int base = kr * BSTR + nq * 4;     // odd stride -> scalar stores
        Bs[base + 0] = b.x;
        Bs[base + 1] = b.y;
        Bs[base + 2] = b.z;
        Bs[base + 3] = b.w;
    }

    // ---- prefetch A tile 0 ----
    {
        #pragma unroll
        for (int j = 0; j < 2; j++) {
            int idx = tid + j * 256;
            int r   = idx >> 2;
            int kq  = idx & 3;
            int gr  = row0 + r;
            int ok  = (gr < M);
            const float* src = A + (size_t)(ok ? gr : 0) * 128 + kq * 4;
            u32 dst = As_u32 + (u32)(r * ASTR + kq * 4) * 4u;
            cp_async16(dst, src, ok ? 16 : 0);
        }
        cp_async_commit();
    }

    float acc[2][8][4];
    #pragma unroll
    for (int mt = 0; mt < 2; mt++)
        #pragma unroll
        for (int nt = 0; nt < 8; nt++)
            #pragma unroll
            for (int c = 0; c < 4; c++) acc[mt][nt][c] = 0.f;

    for (int kt = 0; kt < 8; kt++) {
        const int k0  = kt * 16;
        const int buf = kt & 1;

        cp_async_wait0();
        __syncthreads();   // A tile ready; orders B STS (iter 0) and buffer reuse

        // prefetch next A tile into the other buffer
        if (kt < 7) {
            int nk0 = k0 + 16;
            #pragma unroll
            for (int j = 0; j < 2; j++) {
                int idx = tid + j * 256;
                int r   = idx >> 2;
                int kq  = idx & 3;
                int gr  = row0 + r;
                int ok  = (gr < M);
                const float* src = A + (size_t)(ok ? gr : 0) * 128 + nk0 + kq * 4;
                u32 dst = As_u32 + (u32)(((buf ^ 1) * A_TILE) + r * ASTR + kq * 4) * 4u;
                cp_async16(dst, src, ok ? 16 : 0);
            }
            cp_async_commit();
        }

        const float* Ab = As + buf * A_TILE;

        // ---- one k16 mma group per tile ----
        u32 ah[2][4], al[2][4], bh[8][2], bl[8][2];
        #pragma unroll
        for (int mt = 0; mt < 2; mt++) {
            int m  = warpM * 32 + mt * 16 + grp;
            // float2 loads: (row m, k 2t..2t+1), (m+8, same), (m, 2t+8..9), (m+8, 2t+8..9)
            float2 p00 = *(const float2*)&Ab[m * ASTR + 2 * tig];
            float2 p10 = *(const float2*)&Ab[(m + 8) * ASTR + 2 * tig];
            float2 p01 = *(const float2*)&Ab[m * ASTR + 2 * tig + 8];
            float2 p11 = *(const float2*)&Ab[(m + 8) * ASTR + 2 * tig + 8];
            if (RELU) {
                p00.x = fmaxf(p00.x, 0.f); p00.y = fmaxf(p00.y, 0.f);
                p10.x = fmaxf(p10.x, 0.f); p10.y = fmaxf(p10.y, 0.f);
                p01.x = fmaxf(p01.x, 0.f); p01.y = fmaxf(p01.y, 0.f);
                p11.x = fmaxf(p11.x, 0.f); p11.y = fmaxf(p11.y, 0.f);
            }
            ah[mt][0] = pack_bf16_hi(p00.x, p00.y);  al[mt][0] = pack_bf16_lo(p00.x, p00.y);
            ah[mt][1] = pack_bf16_hi(p10.x, p10.y);  al[mt][1] = pack_bf16_lo(p10.x, p10.y);
            ah[mt][2] = pack_bf16_hi(p01.x, p01.y);  al[mt][2] = pack_bf16_lo(p01.x, p01.y);
            ah[mt][3] = pack_bf16_hi(p11.x, p11.y);  al[mt][3] = pack_bf16_lo(p11.x, p11.y);
        }
        #pragma unroll
        for (int nt = 0; nt < 8; nt++) {
            int n = warpN * 64 + nt * 8 + grp;
            float q0 = Bs[(k0 + 2 * tig    ) * BSTR + n];
            float q1 = Bs[(k0 + 2 * tig + 1) * BSTR + n];
            float q2 = Bs[(k0 + 2 * tig + 8) * BSTR + n];
            float q3 = Bs[(k0 + 2 * tig + 9) * BSTR + n];
            bh[nt][0] = pack_bf16_hi(q0, q1);  bl[nt][0] = pack_bf16_lo(q0, q1);
            bh[nt][1] = pack_bf16_hi(q2, q3);  bl[nt][1] = pack_bf16_lo(q2, q3);
        }

        // Batched issue: 16 independent mmas between dependent accumulator writes.
        #pragma unroll
        for (int mt = 0; mt < 2; mt++)
            #pragma unroll
            for (int nt = 0; nt < 8; nt++)
                mma_bf16(acc[mt][nt], ah[mt], bh[nt]);   // hi*hi
        #pragma unroll
        for (int mt = 0; mt < 2; mt++)
            #pragma unroll
            for (int nt = 0; nt < 8; nt++)
                mma_bf16(acc[mt][nt], ah[mt], bl[nt]);   // hi*lo
        #pragma unroll
        for (int mt = 0; mt < 2; mt++)
            #pragma unroll
            for (int nt = 0; nt < 8; nt++)
                mma_bf16(acc[mt][nt], al[mt], bh[nt]);   // lo*hi

        __syncthreads();   // all reads of buf done before next prefetch overwrites
    }

    // ---- epilogue (C layout identical to tf32 m16n8) ----
    #pragma unroll
    for (int mt = 0; mt < 2; mt++) {
        int r0 = row0 + warpM * 32 + mt * 16 + grp;
        int r1 = r0 + 8;
        #pragma unroll
        for (int nt = 0; nt < 8; nt++) {
            int c = warpN * 64 + nt * 8 + 2 * tig;   // 0..126
            if (relHalf) {
                if (r0 < M) *(float2*)(Z + (size_t)r0 * 128 + c) =
                    make_float2(acc[mt][nt][0], acc[mt][nt][1]);
                if (r1 < M) *(float2*)(Z + (size_t)r1 * 128 + c) =
                    make_float2(acc[mt][nt][2], acc[mt][nt][3]);
            } else {
                float bx = bias[c], by = bias[c + 1];
                if (r0 < M) *(float2*)(H + (size_t)r0 * 128 + c) =
                    make_float2(acc[mt][nt][0] + bx, acc[mt][nt][1] + by);
                if (r1 < M) *(float2*)(H + (size_t)r1 * 128 + c) =
                    make_float2(acc[mt][nt][2] + bx, acc[mt][nt][3] + by);
            }
        }
    }
}

// ---------------------------------------------------------------------------
// CSR gather: one warp per dst node, 8-way unrolled, no atomics.
// ---------------------------------------------------------------------------
__global__ void __launch_bounds__(256)
gather_kernel(const float* __restrict__ Z,
              float* __restrict__ H,
              int Nn)
{
    int warp = (int)((blockIdx.x * (unsigned)blockDim.x + threadIdx.x) >> 5);
    int lane = threadIdx.x & 31;
    if (warp >= Nn) return;

    int lo = g_off[warp];
    int hi = g_off[warp + 1];
    if (lo == hi) return;

    float4 acc = make_float4(0.f, 0.f, 0.f, 0.f);
    int e = lo;
    for (; e + 7 < hi; e += 8) {
        int   s[8]; float w[8]; float4 v[8];
        #pragma unroll
        for (int j = 0; j < 8; j++) { s[j] = g_src[e + j]; w[j] = g_wp[e + j]; }
        #pragma unroll
        for (int j = 0; j < 8; j++)
            v[j] = ((const float4*)(Z + (size_t)s[j] * 128))[lane];
        #pragma unroll
        for (int j = 0; j < 8; j++) {
            acc.x = fmaf(w[j], v[j].x, acc.x);
            acc.y = fmaf(w[j], v[j].y, acc.y);
            acc.z = fmaf(w[j], v[j].z, acc.z);
            acc.w = fmaf(w[j], v[j].w, acc.w);
        }
    }
    for (; e < hi; e++) {
        int   s0 = g_src[e];
        float w0 = g_wp[e];
        float4 v0 = ((const float4*)(Z + (size_t)s0 * 128))[lane];
        acc.x = fmaf(w0, v0.x, acc.x); acc.y = fmaf(w0, v0.y, acc.y);
        acc.z = fmaf(w0, v0.z, acc.z); acc.w = fmaf(w0, v0.w, acc.w);
    }

    float4* hp = ((float4*)(H + (size_t)warp * 128)) + lane;
    float4 h = *hp;
    h.x += acc.x; h.y += acc.y; h.z += acc.z; h.w += acc.w;
    *hp = h;
}

// ---------------------------------------------------------------------------
// Pool + linear + sigmoid; re-zeroes g_deg for the next call.
// ---------------------------------------------------------------------------
__global__ void __launch_bounds__(128)
pool_kernel(const float* __restrict__ H2,
            const float* __restrict__ Wlin,
            const float* __restrict__ blin,
            float* __restrict__ out,
            int Nn)
{
    int g = blockIdx.x;
    int t = threadIdx.x;

    for (int i = g * 128 + t; i < Nn; i += gridDim.x * 128)
        g_deg[i] = 0;

    __shared__ int s_range[2];
    if (t < 2) {
        int target = g + t;
        int lo = 0, hi = Nn;
        while (lo < hi) {
            int mid = (lo + hi) >> 1;
            if (g_batch[mid] < target) lo = mid + 1; else hi = mid;
        }
        s_range[t] = lo;
    }
    __syncthreads();
    int lo = s_range[0], hi = s_range[1];

    float m = -INFINITY;
    for (int n = lo; n < hi; n++)
        m = fmaxf(m, H2[(size_t)n * 128 + t]);
    if (hi > lo) m = fmaxf(m, 0.0f);

    float v = m * Wlin[t];

    __shared__ float red[128];
    red[t] = v;
    __syncthreads();
    #pragma unroll
    for (int s = 64; s > 0; s >>= 1) {
        if (t < s) red[t] += red[t + s];
        __syncthreads();
    }
    if (t == 0) {
        float logit = red[0] + blin[0];
        out[g] = 1.0f / (1.0f + expf(-logit));
    }
}

// ---------------------------------------------------------------------------
extern "C" void kernel_launch(void* const* d_in, const int* in_sizes, int n_in,
                              void* d_out, int out_size)
{
    const float* x      = (const float*) d_in[0];
    const int*   ei     = (const int*)   d_in[1];
    const int*   batch  = (const int*)   d_in[2];
    const float* ew     = (const float*) d_in[3];
    const float* W1rel  = (const float*) d_in[4];
    const float* b1     = (const float*) d_in[5];
    const float* W1root = (const float*) d_in[6];
    const float* W2rel  = (const float*) d_in[7];
    const float* b2     = (const float*) d_in[8];
    const float* W2root = (const float*) d_in[9];
    const float* Wlin   = (const float*) d_in[10];
    const float* blin   = (const float*) d_in[11];
    float* out = (float*)d_out;

    int M = in_sizes[0] / 128;
    int E = in_sizes[1] / 2;
    int G = out_size;
    if (M > MAX_NODES) M = MAX_NODES;
    if (E > MAX_EDGES) E = MAX_EDGES;

    float *Z, *H1, *H2;
    cudaGetSymbolAddress((void**)&Z,  g_Z);
    cudaGetSymbolAddress((void**)&H1, g_H1);
    cudaGetSymbolAddress((void**)&H2, g_H2);

    // Allow >48KB dynamic smem for the GEMM.  Idempotent host-side attribute
    // registration (not a stream op; safe under graph capture).
    cudaFuncSetAttribute(gemm_dual<false>,
        cudaFuncAttributeMaxDynamicSharedMemorySize, GEMM_SMEM_BYTES);
    cudaFuncSetAttribute(gemm_dual<true>,
        cudaFuncAttributeMaxDynamicSharedMemorySize, GEMM_SMEM_BYTES);

    int NB = (M + SCAN_CHUNK - 1) / SCAN_CHUNK;
    dim3 ggrid((M + 127) / 128, 2);
    int gatherBlocks = (M * 32 + 255) / 256;

    // 1: convert + detect + histogram
    {
        int work = 2 * E;
        if (M > work) work = M;
        convert_hist<<<(work + 255) / 256, 256>>>(ei, batch, E, M);
    }
    // 2-3: scan front half
    partial_kernel  <<<NB, 256>>>(M);
    scan_part_kernel<<<1, 64>>>(NB, M);
    // 4: Layer-1 GEMM (no CSR dependence) -- profiled launch
    gemm_dual<false><<<ggrid, 256, GEMM_SMEM_BYTES>>>(x, W1rel, W1root, b1, Z, H1, M);
    // 5-6: finish CSR build
    writeoff_kernel <<<NB, 256>>>(M);
    fill_kernel<<<(E + 255) / 256, 256>>>(ew, E, M);
    // 7: Layer-1 gather
    gather_kernel<<<gatherBlocks, 256>>>(Z, H1, M);
    // 8-9: Layer 2
    gemm_dual<true><<<ggrid, 256, GEMM_SMEM_BYTES>>>(H1, W2rel, W2root, b2, Z, H2, M);
    gather_kernel<<<gatherBlocks, 256>>>(Z, H2, M);
    // 10: Pool + linear + sigmoid (+ deg re-zero)
    pool_kernel<<<G, 128>>>(H2, Wlin, blin, out, M);
}

// round 17
// speedup vs baseline: 1.2378x; 1.0282x over previous
#include <cuda_runtime.h>
#include <math.h>

// ---------------------------------------------------------------------------
// simpleGNN: 2x GraphConv(128->128) + ReLU, segment_max pool, Linear(128->1),
// sigmoid.
// GEMM-first reordering; CSR gather (no float atomics); parallel CSR build.
// R17: B pre-packed to bf16 hi/lo planes at resident-load time, with column
//      remap c' = (n%8)*16 + n/8 so fragment loads are uint4 (8 LDS.128/tile
//      vs 32 LDS.32).  R16 ncu: L1=62.4% top, tensor=30.2% => smem-bound.
//      mma math unchanged (bf16 m16n8k16, hh+hl+lh truncation split).
// ---------------------------------------------------------------------------

#define MAX_NODES 50000
#define MAX_EDGES 640000
#define FDIM      128
#define SCAN_CHUNK 1024
#define MAX_PARTS  64

#define ASTR 20
#define A_TILE (128 * ASTR)                  // floats per A buffer
#define BP_STRIDE 132                        // u32 words per kpair row (==4 mod 32)
#define BP_PLANE  (64 * BP_STRIDE)           // u32 words per plane
#define GEMM_SMEM_BYTES ((2 * BP_PLANE + 2 * A_TILE) * 4)

typedef unsigned int u32;

__device__ float g_Z    [MAX_NODES * FDIM];
__device__ float g_H1   [MAX_NODES * FDIM];
__device__ float g_H2   [MAX_NODES * FDIM];
__device__ int   g_ei   [2 * MAX_EDGES];
__device__ int   g_batch[MAX_NODES];
__device__ int   g_deg  [MAX_NODES];
__device__ int   g_off  [MAX_NODES + 1];
__device__ int   g_part [MAX_PARTS];
__device__ int   g_src  [MAX_EDGES];
__device__ float g_wp   [MAX_EDGES];

// ---------------- bf16 split helpers ----------------------------------------
// hi = bf16 truncation of f (top 16 bits); residual exact in fp32; lo = rn(r).
__device__ __forceinline__ u32 pack_bf16_hi(float f0, float f1) {
    u32 d;
    asm("prmt.b32 %0, %1, %2, 0x7632;"
        : "=r"(d) : "r"(__float_as_uint(f0)), "r"(__float_as_uint(f1)));
    return d;
}
__device__ __forceinline__ u32 pack_bf16_lo(float f0, float f1) {
    float t0 = __uint_as_float(__float_as_uint(f0) & 0xFFFF0000u);
    float t1 = __uint_as_float(__float_as_uint(f1) & 0xFFFF0000u);
    float r0 = f0 - t0;
    float r1 = f1 - t1;
    u32 d;
    asm("cvt.rn.bf16x2.f32 %0, %1, %2;" : "=r"(d) : "f"(r1), "f"(r0));
    return d;
}
__device__ __forceinline__ void mma_bf16(float c[4], const u32 a[4], const u32 b[2]) {
    asm("mma.sync.aligned.m16n8k16.row.col.f32.bf16.bf16.f32 "
        "{%0,%1,%2,%3}, {%4,%5,%6,%7}, {%8,%9}, {%0,%1,%2,%3};"
        : "+f"(c[0]), "+f"(c[1]), "+f"(c[2]), "+f"(c[3])
        : "r"(a[0]), "r"(a[1]), "r"(a[2]), "r"(a[3]), "r"(b[0]), "r"(b[1]));
}
__device__ __forceinline__ void cp_async16(u32 smem_dst, const void* gsrc, int src_bytes) {
    asm volatile("cp.async.ca.shared.global [%0], [%1], 16, %2;"
                 :: "r"(smem_dst), "l"(gsrc), "r"(src_bytes));
}
__device__ __forceinline__ void cp_async_commit() {
    asm volatile("cp.async.commit_group;");
}
__device__ __forceinline__ void cp_async_wait0() {
    asm volatile("cp.async.wait_group 0;");
}

// ---------------------------------------------------------------------------
// convert + histogram + dtype detect (fused).
// ---------------------------------------------------------------------------
__global__ void __launch_bounds__(256)
convert_hist(const int* __restrict__ ei,
             const int* __restrict__ batch,
             int E, int Nn)
{
    __shared__ int s_is64;
    if (threadIdx.x == 0) {
        int any = 0;
        #pragma unroll
        for (int k = 1; k < 128; k += 2) any |= ei[k];
        s_is64 = (any == 0);
    }
    __syncthreads();
    int f = s_is64;

    int i = blockIdx.x * blockDim.x + threadIdx.x;
    int twoE = 2 * E;
    if (i < twoE) {
        int v = f ? ei[2 * i] : ei[i];
        g_ei[i] = v;
        if (i >= E && (unsigned)v < (unsigned)Nn)
            atomicAdd(&g_deg[v], 1);
    }
    if (i < Nn)
        g_batch[i] = f ? batch[2 * i] : batch[i];
}

// ---------------------------------------------------------------------------
// Blocked exclusive scan of g_deg -> g_off.
// ---------------------------------------------------------------------------
__global__ void __launch_bounds__(256)
partial_kernel(int Nn)
{
    __shared__ int red[256];
    int t = threadIdx.x;
    int base = blockIdx.x * SCAN_CHUNK + t * 4;
    int s = 0;
    #pragma unroll
    for (int j = 0; j < 4; j++) {
        int idx = base + j;
        s += (idx < Nn) ? g_deg[idx] : 0;
    }
    red[t] = s;
    __syncthreads();
    #pragma unroll
    for (int d = 128; d > 0; d >>= 1) {
        if (t < d) red[t] += red[t + d];
        __syncthreads();
    }
    if (t == 0) g_part[blockIdx.x] = red[0];
}

__global__ void __launch_bounds__(64)
scan_part_kernel(int NB, int Nn)
{
    __shared__ int s[MAX_PARTS];
    int t = threadIdx.x;
    s[t] = (t < NB) ? g_part[t] : 0;
    __syncthreads();
    #pragma unroll
    for (int d = 1; d < MAX_PARTS; d <<= 1) {
        int v = (t >= d) ? s[t - d] : 0;
        __syncthreads();
        s[t] += v;
        __syncthreads();
    }
    if (t < NB) g_part[t] = (t == 0) ? 0 : s[t - 1];
    if (t == MAX_PARTS - 1) g_off[Nn] = s[MAX_PARTS - 1];
}

__global__ void __launch_bounds__(256)
writeoff_kernel(int Nn)
{
    __shared__ int sums[256];
    int t = threadIdx.x;
    int base = blockIdx.x * SCAN_CHUNK + t * 4;

    int local[4];
    int s = 0;
    #pragma unroll
    for (int j = 0; j < 4; j++) {
        int idx = base + j;
        local[j] = (idx < Nn) ? g_deg[idx] : 0;
        s += local[j];
    }
    sums[t] = s;
    __syncthreads();
    #pragma unroll
    for (int d = 1; d < 256; d <<= 1) {
        int v = (t >= d) ? sums[t - d] : 0;
        __syncthreads();
        sums[t] += v;
        __syncthreads();
    }
    int run = g_part[blockIdx.x] + ((t == 0) ? 0 : sums[t - 1]);
    #pragma unroll
    for (int j = 0; j < 4; j++) {
        int idx = base + j;
        if (idx < Nn) {
            g_off[idx] = run;
            g_deg[idx] = run;
            run += local[j];
        }
    }
}

__global__ void __launch_bounds__(256)
fill_kernel(const float* __restrict__ ew, int E, int Nn)
{
    int i = blockIdx.x * blockDim.x + threadIdx.x;
    if (i >= E) return;
    int s = g_ei[i];
    int d = g_ei[E + i];
    if ((unsigned)s >= (unsigned)Nn || (unsigned)d >= (unsigned)Nn) return;
    int p = atomicAdd(&g_deg[d], 1);
    g_src[p] = s;
    g_wp[p]  = ew[i];
}

// ---------------------------------------------------------------------------
// Dual-output GEMM (bf16 m16n8k16, hh+hl+lh truncation split).
//   y==0: Z[m,:] = act(A[m,:]) @ Wrel       (cols 0..127)
//   y==1: H[m,:] = act(A[m,:]) @ Wroot + b  (cols 128..255)
// Block tile 128x128, BK=16, 256 threads (8 warps: 4m x 2n, warp tile 32x64).
// B pre-packed to bf16 hi/lo planes at resident-load time:
//   plane[kpair][c'] with c' = (n%8)*16 + n/8; word = (bf16(B[2kp][n]),
//   bf16(B[2kp+1][n])).  Fragment loads are uint4 (8 nt contiguous),
//   stride 132 words (==4 mod 32 -> verified conflict-free).
// A fp32 double-buffered via cp.async (stride 20), packed in registers.
// ---------------------------------------------------------------------------
template<bool RELU>
__global__ void __launch_bounds__(256)
gemm_dual(const float* __restrict__ A,
          const float* __restrict__ Wrel,
          const float* __restrict__ Wroot,
          const float* __restrict__ bias,
          float* __restrict__ Z,
          float* __restrict__ H,
          int M)
{
    extern __shared__ __align__(16) u32 smem_u[];
    u32*   Bph = smem_u;                    // hi plane
    u32*   Bpl = smem_u + BP_PLANE;         // lo plane
    float* As  = (float*)(smem_u + 2 * BP_PLANE);

    const int tid   = threadIdx.x;
    const int wid   = tid >> 5;
    const int lane  = tid & 31;
    const int grp   = lane >> 2;      // 0..7
    const int tig   = lane & 3;       // 0..3
    const int warpM = wid >> 1;       // 0..3  (32-row strip)
    const int warpN = wid & 1;        // 0..1  (64-col strip)
    const int row0  = blockIdx.x * 128;
    const bool relHalf = (blockIdx.y == 0);
    const float* __restrict__ W = relHalf ? Wrel : Wroot;

    const u32 As_u32 = (u32)__cvta_generic_to_shared(As);

    // ---- one-time: pack FULL B (128x128) into bf16 hi/lo planes ----
    #pragma unroll
    for (int it = 0; it < 32; it++) {
        int idx   = tid + it * 256;        // 0..8191 (kpair, n)
        int kpair = idx >> 7;              // 0..63
        int n     = idx & 127;
        float f0 = W[(size_t)(2 * kpair    ) * 128 + n];
        float f1 = W[(size_t)(2 * kpair + 1) * 128 + n];
        int cprime = (n & 7) * 16 + (n >> 3);
        Bph[kpair * BP_STRIDE + cprime] = pack_bf16_hi(f0, f1);
        Bpl[kpair * BP_STRIDE + cprime] = pack_bf16_lo(f0, f1);
    }

    // ---- prefetch A tile 0 ----
    {
        #pragma unroll
        for (int j = 0; j < 2; j++) {
            int idx = tid + j * 256;
            int r   = idx >> 2;
            int kq  = idx & 3;
            int gr  = row0 + r;
            int ok  = (gr < M);
            const float* src = A + (size_t)(ok ? gr : 0) * 128 + kq * 4;
            u32 dst = As_u32 + (u32)(r * ASTR + kq * 4) * 4u;
            cp_async16(dst, src, ok ? 16 : 0);
        }
        cp_async_commit();
    }

    float acc[2][8][4];
    #pragma unroll
    for (int mt = 0; mt < 2; mt++)
        #pragma unroll
        for (int nt = 0; nt < 8; nt++)
            #pragma unroll
            for (int c = 0; c < 4; c++) acc[mt][nt][c] = 0.f;

    const int cbase = grp * 16 + warpN * 8;

    for (int kt = 0; kt < 8; kt++) {
        const int k0  = kt * 16;
        const int buf = kt & 1;

        cp_async_wait0();
        __syncthreads();   // A tile ready; orders B pack (iter 0) and buffer reuse

        // prefetch next A tile into the other buffer
        if (kt < 7) {
            int nk0 = k0 + 16;
            #pragma unroll
            for (int j = 0; j < 2; j++) {
                int idx = tid + j * 256;
                int r   = idx >> 2;
                int kq  = idx & 3;
                int gr  = row0 + r;
                int ok  = (gr < M);
                const float* src = A + (size_t)(ok ? gr : 0) * 128 + nk0 + kq * 4;
                u32 dst = As_u32 + (u32)(((buf ^ 1) * A_TILE) + r * ASTR + kq * 4) * 4u;
                cp_async16(dst, src, ok ? 16 : 0);
            }
            cp_async_commit();
        }

        const float* Ab = As + buf * A_TILE;

        // ---- A fragments: fp32 LDS + register bf16 packing ----
        u32 ah[2][4], al[2][4];
        #pragma unroll
        for (int mt = 0; mt < 2; mt++) {
            int m  = warpM * 32 + mt * 16 + grp;
            float2 p00 = *(const float2*)&Ab[m * ASTR + 2 * tig];
            float2 p10 = *(const float2*)&Ab[(m + 8) * ASTR + 2 * tig];
            float2 p01 = *(const float2*)&Ab[m * ASTR + 2 * tig + 8];
            float2 p11 = *(const float2*)&Ab[(m + 8) * ASTR + 2 * tig + 8];
            if (RELU) {
                p00.x = fmaxf(p00.x, 0.f); p00.y = fmaxf(p00.y, 0.f);
                p10.x = fmaxf(p10.x, 0.f); p10.y = fmaxf(p10.y, 0.f);
                p01.x = fmaxf(p01.x, 0.f); p01.y = fmaxf(p01.y, 0.f);
                p11.x = fmaxf(p11.x, 0.f); p11.y = fmaxf(p11.y, 0.f);
            }
            ah[mt][0] = pack_bf16_hi(p00.x, p00.y);  al[mt][0] = pack_bf16_lo(p00.x, p00.y);
            ah[mt][1] = pack_bf16_hi(p10.x, p10.y);  al[mt][1] = pack_bf16_lo(p10.x, p10.y);
            ah[mt][2] = pack_bf16_hi(p01.x, p01.y);  al[mt][2] = pack_bf16_lo(p01.x, p01.y);
            ah[mt][3] = pack_bf16_hi(p11.x, p11.y);  al[mt][3] = pack_bf16_lo(p11.x, p11.y);
        }

        // ---- B fragments: pre-packed planes, uint4 loads ----
        u32 bh[8][2], bl[8][2];
        {
            int kp = (k0 >> 1) + tig;              // kpair row for b[*][0]
            const uint4* h0 = (const uint4*)&Bph[kp * BP_STRIDE + cbase];
            const uint4* h1 = (const uint4*)&Bph[(kp + 4) * BP_STRIDE + cbase];
            const uint4* l0 = (const uint4*)&Bpl[kp * BP_STRIDE + cbase];
            const uint4* l1 = (const uint4*)&Bpl[(kp + 4) * BP_STRIDE + cbase];
            uint4 ha = h0[0], hb = h0[1];          // nt 0..3, 4..7  (b[nt][0])
            uint4 hc = h1[0], hd = h1[1];          // nt 0..3, 4..7  (b[nt][1])
            uint4 la = l0[0], lb = l0[1];
            uint4 lc = l1[0], ld = l1[1];
            bh[0][0]=ha.x; bh[1][0]=ha.y; bh[2][0]=ha.z; bh[3][0]=ha.w;
            bh[4][0]=hb.x; bh[5][0]=hb.y; bh[6][0]=hb.z; bh[7][0]=hb.w;
            bh[0][1]=hc.x; bh[1][1]=hc.y; bh[2][1]=hc.z; bh[3][1]=hc.w;
            bh[4][1]=hd.x; bh[5][1]=hd.y; bh[6][1]=hd.z; bh[7][1]=hd.w;
            bl[0][0]=la.x; bl[1][0]=la.y; bl[2][0]=la.z; bl[3][0]=la.w;
            bl[4][0]=lb.x; bl[5][0]=lb.y; bl[6][0]=lb.z; bl[7][0]=lb.w;
            bl[0][1]=lc.x; bl[1][1]=lc.y; bl[2][1]=lc.z; bl[3][1]=lc.w;
            bl[4][1]=ld.x; bl[5][1]=ld.y; bl[6][1]=ld.z; bl[7][1]=ld.w;
        }

        // Batched issue: 16 independent mmas between dependent accumulator writes.
        #pragma unroll
        for (int mt = 0; mt < 2; mt++)
            #pragma unroll
            for (int nt = 0; nt < 8; nt++)
                mma_bf16(acc[mt][nt], ah[mt], bh[nt]);   // hi*hi
        #pragma unroll
        for (int mt = 0; mt < 2; mt++)
            #pragma unroll
            for (int nt = 0; nt < 8; nt++)
                mma_bf16(acc[mt][nt], ah[mt], bl[nt]);   // hi*lo
        #pragma unroll
        for (int mt = 0; mt < 2; mt++)
            #pragma unroll
            for (int nt = 0; nt < 8; nt++)
                mma_bf16(acc[mt][nt], al[mt], bh[nt]);   // lo*hi

        __syncthreads();   // all reads of buf done before next prefetch overwrites
    }

    // ---- epilogue (C layout identical) ----
    #pragma unroll
    for (int mt = 0; mt < 2; mt++) {
        int r0 = row0 + warpM * 32 + mt * 16 + grp;
        int r1 = r0 + 8;
        #pragma unroll
        for (int nt = 0; nt < 8; nt++) {
            int c = warpN * 64 + nt * 8 + 2 * tig;   // 0..126
            if (relHalf) {
                if (r0 < M) *(float2*)(Z + (size_t)r0 * 128 + c) =
                    make_float2(acc[mt][nt][0], acc[mt][nt][1]);
                if (r1 < M) *(float2*)(Z + (size_t)r1 * 128 + c) =
                    make_float2(acc[mt][nt][2], acc[mt][nt][3]);
            } else {
                float bx = bias[c], by = bias[c + 1];
                if (r0 < M) *(float2*)(H + (size_t)r0 * 128 + c) =
                    make_float2(acc[mt][nt][0] + bx, acc[mt][nt][1] + by);
                if (r1 < M) *(float2*)(H + (size_t)r1 * 128 + c) =
                    make_float2(acc[mt][nt][2] + bx, acc[mt][nt][3] + by);
            }
        }
    }
}

// ---------------------------------------------------------------------------
// CSR gather: one warp per dst node, 8-way unrolled, no atomics.
// ---------------------------------------------------------------------------
__global__ void __launch_bounds__(256)
gather_kernel(const float* __restrict__ Z,
              float* __restrict__ H,
              int Nn)
{
    int warp = (int)((blockIdx.x * (unsigned)blockDim.x + threadIdx.x) >> 5);
    int lane = threadIdx.x & 31;
    if (warp >= Nn) return;

    int lo = g_off[warp];
    int hi = g_off[warp + 1];
    if (lo == hi) return;

    float4 acc = make_float4(0.f, 0.f, 0.f, 0.f);
    int e = lo;
    for (; e + 7 < hi; e += 8) {
        int   s[8]; float w[8]; float4 v[8];
        #pragma unroll
        for (int j = 0; j < 8; j++) { s[j] = g_src[e + j]; w[j] = g_wp[e + j]; }
        #pragma unroll
        for (int j = 0; j < 8; j++)
            v[j] = ((const float4*)(Z + (size_t)s[j] * 128))[lane];
        #pragma unroll
        for (int j = 0; j < 8; j++) {
            acc.x = fmaf(w[j], v[j].x, acc.x);
            acc.y = fmaf(w[j], v[j].y, acc.y);
            acc.z = fmaf(w[j], v[j].z, acc.z);
            acc.w = fmaf(w[j], v[j].w, acc.w);
        }
    }
    for (; e < hi; e++) {
        int   s0 = g_src[e];
        float w0 = g_wp[e];
        float4 v0 = ((const float4*)(Z + (size_t)s0 * 128))[lane];
        acc.x = fmaf(w0, v0.x, acc.x); acc.y = fmaf(w0, v0.y, acc.y);
        acc.z = fmaf(w0, v0.z, acc.z); acc.w = fmaf(w0, v0.w, acc.w);
    }

    float4* hp = ((float4*)(H + (size_t)warp * 128)) + lane;
    float4 h = *hp;
    h.x += acc.x; h.y += acc.y; h.z += acc.z; h.w += acc.w;
    *hp = h;
}

// ---------------------------------------------------------------------------
// Pool + linear + sigmoid; re-zeroes g_deg for the next call.
// ---------------------------------------------------------------------------
__global__ void __launch_bounds__(128)
pool_kernel(const float* __restrict__ H2,
            const float* __restrict__ Wlin,
            const float* __restrict__ blin,
            float* __restrict__ out,
            int Nn)
{
    int g = blockIdx.x;
    int t = threadIdx.x;

    for (int i = g * 128 + t; i < Nn; i += gridDim.x * 128)
        g_deg[i] = 0;

    __shared__ int s_range[2];
    if (t < 2) {
        int target = g + t;
        int lo = 0, hi = Nn;
        while (lo < hi) {
            int mid = (lo + hi) >> 1;
            if (g_batch[mid] < target) lo = mid + 1; else hi = mid;
        }
        s_range[t] = lo;
    }
    __syncthreads();
    int lo = s_range[0], hi = s_range[1];

    float m = -INFINITY;
    for (int n = lo; n < hi; n++)
        m = fmaxf(m, H2[(size_t)n * 128 + t]);
    if (hi > lo) m = fmaxf(m, 0.0f);

    float v = m * Wlin[t];

    __shared__ float red[128];
    red[t] = v;
    __syncthreads();
    #pragma unroll
    for (int s = 64; s > 0; s >>= 1) {
        if (t < s) red[t] += red[t + s];
        __syncthreads();
    }
    if (t == 0) {
        float logit = red[0] + blin[0];
        out[g] = 1.0f / (1.0f + expf(-logit));
    }
}

// ---------------------------------------------------------------------------
extern "C" void kernel_launch(void* const* d_in, const int* in_sizes, int n_in,
                              void* d_out, int out_size)
{
    const float* x      = (const float*) d_in[0];
    const int*   ei     = (const int*)   d_in[1];
    const int*   batch  = (const int*)   d_in[2];
    const float* ew     = (const float*) d_in[3];
    const float* W1rel  = (const float*) d_in[4];
    const float* b1     = (const float*) d_in[5];
    const float* W1root = (const float*) d_in[6];
    const float* W2rel  = (const float*) d_in[7];
    const float* b2     = (const float*) d_in[8];
    const float* W2root = (const float*) d_in[9];
    const float* Wlin   = (const float*) d_in[10];
    const float* blin   = (const float*) d_in[11];
    float* out = (float*)d_out;

    int M = in_sizes[0] / 128;
    int E = in_sizes[1] / 2;
    int G = out_size;
    if (M > MAX_NODES) M = MAX_NODES;
    if (E > MAX_EDGES) E = MAX_EDGES;

    float *Z, *H1, *H2;
    cudaGetSymbolAddress((void**)&Z,  g_Z);
    cudaGetSymbolAddress((void**)&H1, g_H1);
    cudaGetSymbolAddress((void**)&H2, g_H2);

    // Allow >48KB dynamic smem for the GEMM.  Idempotent host-side attribute
    // registration (not a stream op; safe under graph capture).
    cudaFuncSetAttribute(gemm_dual<false>,
        cudaFuncAttributeMaxDynamicSharedMemorySize, GEMM_SMEM_BYTES);
    cudaFuncSetAttribute(gemm_dual<true>,
        cudaFuncAttributeMaxDynamicSharedMemorySize, GEMM_SMEM_BYTES);

    int NB = (M + SCAN_CHUNK - 1) / SCAN_CHUNK;
    dim3 ggrid((M + 127) / 128, 2);
    int gatherBlocks = (M * 32 + 255) / 256;

    // 1: convert + detect + histogram
    {
        int work = 2 * E;
        if (M > work) work = M;
        convert_hist<<<(work + 255) / 256, 256>>>(ei, batch, E, M);
    }
    // 2-3: scan front half
    partial_kernel  <<<NB, 256>>>(M);
    scan_part_kernel<<<1, 64>>>(NB, M);
    // 4: Layer-1 GEMM (no CSR dependence) -- profiled launch
    gemm_dual<false><<<ggrid, 256, GEMM_SMEM_BYTES>>>(x, W1rel, W1root, b1, Z, H1, M);
    // 5-6: finish CSR build
    writeoff_kernel <<<NB, 256>>>(M);
    fill_kernel<<<(E + 255) / 256, 256>>>(ew, E, M);
    // 7: Layer-1 gather
    gather_kernel<<<gatherBlocks, 256>>>(Z, H1, M);
    // 8-9: Layer 2
    gemm_dual<true><<<ggrid, 256, GEMM_SMEM_BYTES>>>(H1, W2rel, W2root, b2, Z, H2, M);
    gather_kernel<<<gatherBlocks, 256>>>(Z, H2, M);
    // 10: Pool + linear + sigmoid (+ deg re-zero)
    pool_kernel<<<G, 128>>>(H2, Wlin, blin, out, M);
}